// round 7
// baseline (speedup 1.0000x reference)
#include <cuda_runtime.h>
#include <math.h>
#include <stdint.h>

#define T_SEQ 4096
#define NCTA  128

// ---------------- scratch (static device allocations; no runtime alloc) ---------------
__device__ float g_ys1[T_SEQ * 2048];     // e1 outputs
__device__ float g_ys2[T_SEQ * 1024];     // d1 outputs
__device__ float g_ys3[T_SEQ * 2048];     // d2 outputs
__device__ float g_xg_e2[T_SEQ * 3072];   // e2 input projections
__device__ float g_xg_d2[(size_t)T_SEQ * 6144];   // d2 input projections
__device__ float g_xgc_d1[3072];          // d1 constant input projection
__device__ float g_h_e1[2 * 2048];
__device__ float g_h_e2[2 * 1024];
__device__ float g_h_d1[2 * 1024];
__device__ float g_h_d2[2 * 2048];
__device__ unsigned g_flags[4][NCTA];     // per-layer per-CTA step counters
__device__ unsigned g_epochs[4][8 * 32];  // per-layer epoch, replicated in 8 L2 lines

// ---------------- init: zero hidden-state double buffers + barrier state ----------------
__global__ void init_h_kernel() {
    int i = blockIdx.x * blockDim.x + threadIdx.x;
    if (i < 2 * 2048) { g_h_e1[i] = 0.f; g_h_d2[i] = 0.f; }
    if (i < 2 * 1024) { g_h_e2[i] = 0.f; g_h_d1[i] = 0.f; }
    if (i < 4 * NCTA) ((unsigned*)g_flags)[i] = 0u;
    if (i < 4 * 8 * 32) ((unsigned*)g_epochs)[i] = 0u;
}

__device__ __forceinline__ unsigned ld_relaxed_gpu(const unsigned* p) {
    unsigned v;
    asm volatile("ld.relaxed.gpu.global.b32 %0, [%1];" : "=r"(v) : "l"(p) : "memory");
    return v;
}
__device__ __forceinline__ unsigned ld_acquire_gpu(const unsigned* p) {
    unsigned v;
    asm volatile("ld.acquire.gpu.global.b32 %0, [%1];" : "=r"(v) : "l"(p) : "memory");
    return v;
}
__device__ __forceinline__ void st_release_gpu(unsigned* p, unsigned v) {
    asm volatile("st.release.gpu.global.b32 [%0], %1;" :: "l"(p), "r"(v) : "memory");
}

// ---------------- persistent GRU recurrence kernel -------------------------------------
// Grid = NCTA + 1. CTA NCTA is a dedicated barrier aggregator: it polls the
// per-CTA flags and republishes a replicated epoch word. Worker CTAs poll only
// their epoch replica (<=16 pollers per L2 line). The aggregator is always
// parked at the poll when the last flag lands, so hop-1 detection fully
// overlaps worker compute.
// MODE 0: xg from scalar input x[t] (e1).  MODE 1: xg precomputed [T,3H] (e2,d2).
// MODE 2: xg constant [3H] (d1).
// KS: K-prefix of every row cached in SMEM (KS == H -> fully resident).
template<int H, int NTH, int MODE, bool STORE_YS, int KS>
__global__ void __launch_bounds__(NTH, 1) gru_rec_kernel(
    const float* __restrict__ Whh, const float* __restrict__ bhh,
    const float* __restrict__ xg,   // MODE 1
    const float* __restrict__ xgc,  // MODE 2
    const float* __restrict__ x,    // MODE 0
    const float* __restrict__ wih1, // MODE 0: Wih column 0, [3H]
    const float* __restrict__ bih,  // MODE 0
    float* __restrict__ hbuf,       // [2*H] double buffer
    float* __restrict__ ys,         // [T*H] or unused
    int bar_id)
{
    constexpr int NC   = NCTA;
    constexpr int S    = H / NC;     // hidden slice per CTA
    constexpr int ROWS = 3 * S;      // gate rows per CTA
    constexpr int NW   = NTH / 32;
    constexpr int RW   = ROWS / NW;  // rows per warp
    static_assert(ROWS % NW == 0, "rows must divide warps");
    static_assert(KS % 128 == 0 && (H - KS) % 128 == 0, "K chunking");
    static_assert(NTH >= NC, "aggregator needs NC pollers");

    const int tid = threadIdx.x;
    const int bid = blockIdx.x;
    unsigned* flags = &g_flags[bar_id][0];
    unsigned* eps   = &g_epochs[bar_id][0];

    // ---------------- aggregator CTA ----------------
    if (bid == NC) {
        for (int t = 1; t < T_SEQ; t++) {
            if (tid < NC) {
                while (ld_relaxed_gpu(&flags[tid]) < (unsigned)t) { }
                (void)ld_acquire_gpu(&flags[tid]);
            }
            __syncthreads();   // all acquires happen-before the epoch stores
            if (tid < 8) st_release_gpu(&eps[tid * 32], (unsigned)t);
        }
        return;
    }

    // ---------------- worker CTAs ----------------
    extern __shared__ float smem[];
    float* sh_h    = smem;             // [H]
    float* sh_gate = sh_h + H;         // [ROWS]
    float* sh_bhh  = sh_gate + ROWS;   // [ROWS]
    float* sh_xa   = sh_bhh + ROWS;    // [ROWS]
    float* sh_xb   = sh_xa + ROWS;     // [ROWS]
    float* sh_w    = sh_xb + ROWS;     // [ROWS*KS]

    const int c0 = bid * S;
    const unsigned* myep = &eps[(bid & 7) * 32];

    // preload per-row scalars
    for (int lr = tid; lr < ROWS; lr += NTH) {
        int g = lr / S, il = lr - g * S;
        int grow = g * H + c0 + il;
        sh_bhh[lr] = bhh[grow];
        if (MODE == 0) { sh_xa[lr] = wih1[grow]; sh_xb[lr] = bih[grow]; }
        if (MODE == 2) { sh_xa[lr] = xgc[grow]; }
    }
    // preload SMEM-resident K-prefix of every row
    for (int i = tid; i < ROWS * (KS / 4); i += NTH) {
        int lr = i / (KS / 4), k4 = i - lr * (KS / 4);
        int g = lr / S, il = lr - g * S;
        ((float4*)sh_w)[(size_t)lr * (KS / 4) + k4] =
            ((const float4*)(Whh + (size_t)(g * H + c0 + il) * H))[k4];
    }
    __syncthreads();

    const int w = tid >> 5, lane = tid & 31;
    // per-warp row pointers
    const float* wsp[RW];             // smem row base (+ lane offset)
    const float4* wgp[RW];            // global row base as float4 (+ lane)
#pragma unroll
    for (int j = 0; j < RW; j++) {
        int lr = w * RW + j;
        int g = lr / S, il = lr - g * S;
        wsp[j] = sh_w + (size_t)lr * KS + lane * 4;
        wgp[j] = (const float4*)(Whh + (size_t)(g * H + c0 + il) * H) + lane;
    }

    for (int t = 0; t < T_SEQ; t++) {
        // prefetch xg for this step (static data, independent of barrier)
        float pxr = 0.f, pxz = 0.f, pxn = 0.f;
        if (MODE == 1 && tid < S) {
            size_t base = (size_t)t * (3 * H);
            pxr = xg[base + c0 + tid];
            pxz = xg[base + H + c0 + tid];
            pxn = xg[base + 2 * H + c0 + tid];
        }

        // ---- wait: poll our epoch replica (one warp, one line) ------------
        if (tid < 32) {
            while (ld_relaxed_gpu(myep) < (unsigned)t) { }
            (void)ld_acquire_gpu(myep);
        }
        __syncthreads();   // block inherits the acquire's visibility

        // fetch current h from L2 (L1 bypass), vectorized
        const float4* hsrc = (const float4*)(hbuf + (t & 1) * H);
        if (tid < H / 4) ((float4*)sh_h)[tid] = __ldcg(hsrc + tid);
        __syncthreads();

        // hg = Whh_slice @ h : K-prefix from SMEM, K-tail streamed from L2
        float acc[RW];
#pragma unroll
        for (int j = 0; j < RW; j++) acc[j] = 0.f;

#pragma unroll
        for (int kb = 0; kb < KS; kb += 128) {
            float4 h4 = *(const float4*)&sh_h[kb + lane * 4];
#pragma unroll
            for (int j = 0; j < RW; j++) {
                float4 w4 = *(const float4*)(wsp[j] + kb);
                acc[j] += w4.x * h4.x + w4.y * h4.y + w4.z * h4.z + w4.w * h4.w;
            }
        }
        if (KS < H) {
#pragma unroll
            for (int kb = KS; kb < H; kb += 128) {
                float4 h4 = *(const float4*)&sh_h[kb + lane * 4];
#pragma unroll
                for (int j = 0; j < RW; j++) {
                    float4 w4 = __ldcg(wgp[j] + kb / 4);
                    acc[j] += w4.x * h4.x + w4.y * h4.y + w4.z * h4.z + w4.w * h4.w;
                }
            }
        }
#pragma unroll
        for (int j = 0; j < RW; j++) {
#pragma unroll
            for (int off = 16; off > 0; off >>= 1)
                acc[j] += __shfl_xor_sync(0xffffffffu, acc[j], off);
            if (lane == 0) sh_gate[w * RW + j] = acc[j] + sh_bhh[w * RW + j];
        }
        __syncthreads();

        // gate math + state update (S threads)
        if (tid < S) {
            int il = tid;
            float hr = sh_gate[il], hz = sh_gate[S + il], hn = sh_gate[2 * S + il];
            float xr, xz, xn;
            if (MODE == 0) {
                float xt = x[t];
                xr = sh_xa[il] * xt + sh_xb[il];
                xz = sh_xa[S + il] * xt + sh_xb[S + il];
                xn = sh_xa[2 * S + il] * xt + sh_xb[2 * S + il];
            } else if (MODE == 1) {
                xr = pxr; xz = pxz; xn = pxn;
            } else {
                xr = sh_xa[il]; xz = sh_xa[S + il]; xn = sh_xa[2 * S + il];
            }
            float r = 1.f / (1.f + expf(-(xr + hr)));
            float z = 1.f / (1.f + expf(-(xz + hz)));
            float n = tanhf(xn + r * hn);
            float hold = sh_h[c0 + il];
            float hnew = (1.f - z) * n + z * hold;
            hbuf[((t + 1) & 1) * H + c0 + il] = hnew;
            if (STORE_YS) ys[(size_t)t * H + c0 + il] = hnew;
        }

        // ---- arrive: bar.sync orders all writers' stores; tid0 releases flag ----
        __syncthreads();
        if (tid == 0) st_release_gpu(&flags[bid], (unsigned)(t + 1));
    }
}

// ---------------- tiled fp32 GEMM: C[M,N] = A[M,K] @ W[N,K]^T + bias[N] -----------------
__global__ void __launch_bounds__(256, 1) gemm_tn_bias(
    const float* __restrict__ A, const float* __restrict__ W,
    const float* __restrict__ bias, float* __restrict__ C,
    int M, int N, int K)
{
    __shared__ float As[8][128];
    __shared__ float Bs[8][128];
    int tid = threadIdx.x;
    int bm = blockIdx.y * 128, bn = blockIdx.x * 128;
    int lr = tid >> 1;
    int lk = (tid & 1) * 4;
    const float* Ap = A + (size_t)(bm + lr) * K + lk;
    const float* Wp = W + (size_t)(bn + lr) * K + lk;
    int tx = tid & 15, ty = tid >> 4;
    int m0 = ty * 8, n0 = tx * 8;

    float acc[8][8];
#pragma unroll
    for (int i = 0; i < 8; i++)
#pragma unroll
        for (int j = 0; j < 8; j++) acc[i][j] = 0.f;

    for (int k0 = 0; k0 < K; k0 += 8) {
        float4 a4 = *(const float4*)Ap;
        float4 b4 = *(const float4*)Wp;
        Ap += 8; Wp += 8;
        As[lk + 0][lr] = a4.x; As[lk + 1][lr] = a4.y;
        As[lk + 2][lr] = a4.z; As[lk + 3][lr] = a4.w;
        Bs[lk + 0][lr] = b4.x; Bs[lk + 1][lr] = b4.y;
        Bs[lk + 2][lr] = b4.z; Bs[lk + 3][lr] = b4.w;
        __syncthreads();
#pragma unroll
        for (int k = 0; k < 8; k++) {
            float a[8], b[8];
            *(float4*)(a)     = *(const float4*)&As[k][m0];
            *(float4*)(a + 4) = *(const float4*)&As[k][m0 + 4];
            *(float4*)(b)     = *(const float4*)&Bs[k][n0];
            *(float4*)(b + 4) = *(const float4*)&Bs[k][n0 + 4];
#pragma unroll
            for (int i = 0; i < 8; i++)
#pragma unroll
                for (int j = 0; j < 8; j++)
                    acc[i][j] += a[i] * b[j];
        }
        __syncthreads();
    }
#pragma unroll
    for (int i = 0; i < 8; i++) {
        int m = bm + m0 + i;
#pragma unroll
        for (int j = 0; j < 8; j++)
            C[(size_t)m * N + bn + n0 + j] = acc[i][j] + bias[bn + n0 + j];
    }
}

// ---------------- one-shot matvec: out[R] = W[R,K] @ v + b ------------------------------
__global__ void matvec_bias(const float* __restrict__ W, const float* __restrict__ b,
                            const float* __restrict__ v, float* __restrict__ out,
                            int R, int K)
{
    int wid = (blockIdx.x * blockDim.x + threadIdx.x) >> 5;
    int lane = threadIdx.x & 31;
    if (wid >= R) return;
    const float* wr = W + (size_t)wid * K;
    float acc = 0.f;
    for (int k = lane; k < K; k += 32) acc += wr[k] * v[k];
#pragma unroll
    for (int off = 16; off; off >>= 1) acc += __shfl_xor_sync(0xffffffffu, acc, off);
    if (lane == 0) out[wid] = acc + b[wid];
}

// ---------------- final projection: out[t] = ys3[t] . outW + outb ----------------------
__global__ void __launch_bounds__(256) final_out_kernel(
    const float* __restrict__ ys3, const float* __restrict__ outW,
    const float* __restrict__ outb, float* __restrict__ out)
{
    __shared__ float red[8];
    int t = blockIdx.x;
    const float* row = ys3 + (size_t)t * 2048;
    float acc = 0.f;
    for (int k = threadIdx.x; k < 2048; k += 256) acc += row[k] * outW[k];
#pragma unroll
    for (int off = 16; off; off >>= 1) acc += __shfl_xor_sync(0xffffffffu, acc, off);
    if ((threadIdx.x & 31) == 0) red[threadIdx.x >> 5] = acc;
    __syncthreads();
    if (threadIdx.x < 8) {
        float v = red[threadIdx.x];
#pragma unroll
        for (int off = 4; off; off >>= 1) v += __shfl_xor_sync(0xffu, v, off);
        if (threadIdx.x == 0) out[t] = v + outb[0];
    }
}

// ---------------- host ------------------------------------------------------------------
extern "C" void kernel_launch(void* const* d_in, const int* in_sizes, int n_in,
                              void* d_out, int out_size)
{
    const float* x       = (const float*)d_in[0];
    const float* e1_Wih  = (const float*)d_in[1];
    const float* e1_Whh  = (const float*)d_in[2];
    const float* e1_bih  = (const float*)d_in[3];
    const float* e1_bhh  = (const float*)d_in[4];
    const float* e2_Wih  = (const float*)d_in[5];
    const float* e2_Whh  = (const float*)d_in[6];
    const float* e2_bih  = (const float*)d_in[7];
    const float* e2_bhh  = (const float*)d_in[8];
    const float* d1_Wih  = (const float*)d_in[9];
    const float* d1_Whh  = (const float*)d_in[10];
    const float* d1_bih  = (const float*)d_in[11];
    const float* d1_bhh  = (const float*)d_in[12];
    const float* d2_Wih  = (const float*)d_in[13];
    const float* d2_Whh  = (const float*)d_in[14];
    const float* d2_bih  = (const float*)d_in[15];
    const float* d2_bhh  = (const float*)d_in[16];
    const float* out_W   = (const float*)d_in[17];
    const float* out_b   = (const float*)d_in[18];
    float* out = (float*)d_out;

    void *p_ys1, *p_ys2, *p_ys3, *p_xg_e2, *p_xg_d2, *p_xgc;
    void *p_h_e1, *p_h_e2, *p_h_d1, *p_h_d2;
    cudaGetSymbolAddress(&p_ys1, g_ys1);
    cudaGetSymbolAddress(&p_ys2, g_ys2);
    cudaGetSymbolAddress(&p_ys3, g_ys3);
    cudaGetSymbolAddress(&p_xg_e2, g_xg_e2);
    cudaGetSymbolAddress(&p_xg_d2, g_xg_d2);
    cudaGetSymbolAddress(&p_xgc, g_xgc_d1);
    cudaGetSymbolAddress(&p_h_e1, g_h_e1);
    cudaGetSymbolAddress(&p_h_e2, g_h_e2);
    cudaGetSymbolAddress(&p_h_d1, g_h_d1);
    cudaGetSymbolAddress(&p_h_d2, g_h_d2);

    // big: H=2048, 128 worker CTAs, 48 rows/CTA, KS=1152 in SMEM
    const int SMEM_BIG   = (2048 + 4 * 48 + 48 * 1152) * 4;   // 230,144 B
    // small: H=1024, 128 worker CTAs, 24 rows/CTA fully resident
    const int SMEM_SMALL = (1024 + 4 * 24 + 24 * 1024) * 4;   // 102,784 B

    auto k_e1 = gru_rec_kernel<2048, 512, 0, true,  1152>;
    auto k_e2 = gru_rec_kernel<1024, 256, 1, false, 1024>;
    auto k_d1 = gru_rec_kernel<1024, 256, 2, true,  1024>;
    auto k_d2 = gru_rec_kernel<2048, 512, 1, true,  1152>;
    cudaFuncSetAttribute(k_e1, cudaFuncAttributeMaxDynamicSharedMemorySize, SMEM_BIG);
    cudaFuncSetAttribute(k_e2, cudaFuncAttributeMaxDynamicSharedMemorySize, SMEM_SMALL);
    cudaFuncSetAttribute(k_d1, cudaFuncAttributeMaxDynamicSharedMemorySize, SMEM_SMALL);
    cudaFuncSetAttribute(k_d2, cudaFuncAttributeMaxDynamicSharedMemorySize, SMEM_BIG);

    init_h_kernel<<<16, 256>>>();

    // e1: GRU(1 -> 2048), store ys1
    k_e1<<<NCTA + 1, 512, SMEM_BIG>>>(e1_Whh, e1_bhh, nullptr, nullptr,
                                      x, e1_Wih, e1_bih,
                                      (float*)p_h_e1, (float*)p_ys1, 0);

    // xg_e2 = ys1 @ e2_Wih^T + e2_bih   [4096,3072]
    gemm_tn_bias<<<dim3(3072 / 128, T_SEQ / 128), 256>>>(
        (const float*)p_ys1, e2_Wih, e2_bih, (float*)p_xg_e2, T_SEQ, 3072, 2048);

    // e2: GRU(2048 -> 1024), only final hT (lands in g_h_e2[0..1024))
    k_e2<<<NCTA + 1, 256, SMEM_SMALL>>>(e2_Whh, e2_bhh, (const float*)p_xg_e2, nullptr,
                                        nullptr, nullptr, nullptr,
                                        (float*)p_h_e2, nullptr, 1);

    // d1 constant input projection: xgc = d1_Wih @ emb + d1_bih
    matvec_bias<<<(3072 * 32) / 256, 256>>>(d1_Wih, d1_bih, (const float*)p_h_e2,
                                            (float*)p_xgc, 3072, 1024);

    // d1: GRU(1024 -> 1024) with constant xg, store ys2
    k_d1<<<NCTA + 1, 256, SMEM_SMALL>>>(d1_Whh, d1_bhh, nullptr, (const float*)p_xgc,
                                        nullptr, nullptr, nullptr,
                                        (float*)p_h_d1, (float*)p_ys2, 2);

    // xg_d2 = ys2 @ d2_Wih^T + d2_bih   [4096,6144]
    gemm_tn_bias<<<dim3(6144 / 128, T_SEQ / 128), 256>>>(
        (const float*)p_ys2, d2_Wih, d2_bih, (float*)p_xg_d2, T_SEQ, 6144, 1024);

    // d2: GRU(1024 -> 2048), store ys3
    k_d2<<<NCTA + 1, 512, SMEM_BIG>>>(d2_Whh, d2_bhh, (const float*)p_xg_d2, nullptr,
                                      nullptr, nullptr, nullptr,
                                      (float*)p_h_d2, (float*)p_ys3, 3);

    // out[t] = ys3[t] . out_W + out_b
    final_out_kernel<<<T_SEQ, 256>>>((const float*)p_ys3, out_W, out_b, out);
}

// round 8
// speedup vs baseline: 1.1085x; 1.1085x over previous
#include <cuda_runtime.h>
#include <cuda_fp16.h>
#include <math.h>
#include <stdint.h>

#define T_SEQ 4096

// ---------------- scratch (static device allocations; no runtime alloc) ---------------
__device__ float g_ys1[T_SEQ * 2048];     // e1 outputs
__device__ float g_ys2[T_SEQ * 1024];     // d1 outputs
__device__ float g_ys3[T_SEQ * 2048];     // d2 outputs
__device__ float g_xg_e2[T_SEQ * 3072];   // e2 input projections
__device__ float g_xg_d2[(size_t)T_SEQ * 6144];   // d2 input projections
__device__ float g_xgc_d1[3072];          // d1 constant input projection
__device__ float g_h_e1[2 * 2048];
__device__ float g_h_e2[2 * 1024];
__device__ float g_h_d1[2 * 1024];
__device__ float g_h_d2[2 * 2048];
__device__ unsigned g_flags[4][128];      // per-layer per-CTA step counters
__device__ unsigned g_epoch[4];           // per-layer aggregated epoch (CTA0-published)
// fp16 copies of the H=2048 recurrent weights (3*2048 x 2048 each, 25 MB each)
__device__ __half g_whh_e1_h[3 * 2048 * 2048];
__device__ __half g_whh_d2_h[3 * 2048 * 2048];

// ---------------- init: zero hidden-state double buffers + barrier state ----------------
__global__ void init_h_kernel() {
    int i = blockIdx.x * blockDim.x + threadIdx.x;
    if (i < 2 * 2048) { g_h_e1[i] = 0.f; g_h_d2[i] = 0.f; }
    if (i < 2 * 1024) { g_h_e2[i] = 0.f; g_h_d1[i] = 0.f; }
    if (i < 4 * 128) ((unsigned*)g_flags)[i] = 0u;
    if (i < 4) g_epoch[i] = 0u;
}

// ---------------- fp32 -> fp16 weight conversion ----------------------------------------
__global__ void convert_half_kernel(const float* __restrict__ src, __half* __restrict__ dst,
                                    int n) {
    int i = blockIdx.x * blockDim.x + threadIdx.x;
    int i4 = i * 4;
    if (i4 + 3 < n) {
        float4 v = *(const float4*)(src + i4);
        dst[i4 + 0] = __float2half(v.x);
        dst[i4 + 1] = __float2half(v.y);
        dst[i4 + 2] = __float2half(v.z);
        dst[i4 + 3] = __float2half(v.w);
    }
}

__device__ __forceinline__ unsigned ld_relaxed_gpu(const unsigned* p) {
    unsigned v;
    asm volatile("ld.relaxed.gpu.global.b32 %0, [%1];" : "=r"(v) : "l"(p) : "memory");
    return v;
}
__device__ __forceinline__ unsigned ld_acquire_gpu(const unsigned* p) {
    unsigned v;
    asm volatile("ld.acquire.gpu.global.b32 %0, [%1];" : "=r"(v) : "l"(p) : "memory");
    return v;
}
__device__ __forceinline__ void st_release_gpu(unsigned* p, unsigned v) {
    asm volatile("st.release.gpu.global.b32 [%0], %1;" :: "l"(p), "r"(v) : "memory");
}

// ---------------- persistent GRU recurrence kernel -------------------------------------
// Two-hop barrier (R6): CTA0 aggregates per-CTA flags into a single epoch word;
// other CTAs poll only the epoch with one warp.
// MODE 0: xg from scalar input x[t] (e1).  MODE 1: xg precomputed [T,3H] (e2,d2).
// MODE 2: xg constant [3H] (d1).
// HALF_W: Whh stored fp16 in SMEM (fully resident). Otherwise fp32 fully resident.
template<int H, int NC, int NTH, int MODE, bool STORE_YS, bool HALF_W>
__global__ void __launch_bounds__(NTH, 1) gru_rec_kernel(
    const void* __restrict__ Whh_v, const float* __restrict__ bhh,
    const float* __restrict__ xg,   // MODE 1
    const float* __restrict__ xgc,  // MODE 2
    const float* __restrict__ x,    // MODE 0
    const float* __restrict__ wih1, // MODE 0: Wih column 0, [3H]
    const float* __restrict__ bih,  // MODE 0
    float* __restrict__ hbuf,       // [2*H] double buffer
    float* __restrict__ ys,         // [T*H] or unused
    int bar_id)
{
    constexpr int S    = H / NC;     // hidden slice per CTA
    constexpr int ROWS = 3 * S;      // gate rows per CTA
    constexpr int NW   = NTH / 32;
    constexpr int RW   = ROWS / NW;  // rows per warp
    static_assert(ROWS % NW == 0, "rows must divide warps");

    extern __shared__ float smem[];
    float* sh_h    = smem;             // [H]
    float* sh_gate = sh_h + H;         // [ROWS]
    float* sh_bhh  = sh_gate + ROWS;   // [ROWS]
    float* sh_xa   = sh_bhh + ROWS;    // [ROWS]
    float* sh_xb   = sh_xa + ROWS;     // [ROWS]
    void*  sh_w    = (void*)(sh_xb + ROWS);   // [ROWS*H] half or float

    const int tid = threadIdx.x;
    const int bid = blockIdx.x;
    const int c0  = bid * S;
    unsigned* flags = &g_flags[bar_id][0];
    unsigned* epoch = &g_epoch[bar_id];

    // preload per-row scalars
    for (int lr = tid; lr < ROWS; lr += NTH) {
        int g = lr / S, il = lr - g * S;
        int grow = g * H + c0 + il;
        sh_bhh[lr] = bhh[grow];
        if (MODE == 0) { sh_xa[lr] = wih1[grow]; sh_xb[lr] = bih[grow]; }
        if (MODE == 2) { sh_xa[lr] = xgc[grow]; }
    }
    // preload ALL weight rows for this CTA (fully SMEM-resident)
    if (HALF_W) {
        const __half* Wh = (const __half*)Whh_v;
        __half* shw = (__half*)sh_w;
        constexpr int U4 = H / 8;   // uint4 per row
        for (int i = tid; i < ROWS * U4; i += NTH) {
            int lr = i / U4, k8 = i - lr * U4;
            int g = lr / S, il = lr - g * S;
            ((uint4*)shw)[(size_t)lr * U4 + k8] =
                ((const uint4*)(Wh + (size_t)(g * H + c0 + il) * H))[k8];
        }
    } else {
        const float* Wf = (const float*)Whh_v;
        float* shw = (float*)sh_w;
        constexpr int U4 = H / 4;   // float4 per row
        for (int i = tid; i < ROWS * U4; i += NTH) {
            int lr = i / U4, k4 = i - lr * U4;
            int g = lr / S, il = lr - g * S;
            ((float4*)shw)[(size_t)lr * U4 + k4] =
                ((const float4*)(Wf + (size_t)(g * H + c0 + il) * H))[k4];
        }
    }
    __syncthreads();

    const int w = tid >> 5, lane = tid & 31;
    // per-warp row pointers into SMEM
    const float* wspf[RW];
    const __half* wsph[RW];
#pragma unroll
    for (int j = 0; j < RW; j++) {
        int lr = w * RW + j;
        if (HALF_W) wsph[j] = (const __half*)sh_w + (size_t)lr * H + lane * 8;
        else        wspf[j] = (const float*)sh_w + (size_t)lr * H + lane * 4;
    }

    for (int t = 0; t < T_SEQ; t++) {
        // prefetch xg for this step (static data, independent of barrier)
        float pxr = 0.f, pxz = 0.f, pxn = 0.f;
        if (MODE == 1 && tid < S) {
            size_t base = (size_t)t * (3 * H);
            pxr = xg[base + c0 + tid];
            pxz = xg[base + H + c0 + tid];
            pxn = xg[base + 2 * H + c0 + tid];
        }

        // ---- wait: two-hop aggregated barrier (R6) -------------------------
        if (bid == 0) {
            if (tid < NC) {
                while (ld_relaxed_gpu(&flags[tid]) < (unsigned)t) { }
                (void)ld_acquire_gpu(&flags[tid]);
            }
            __syncthreads();
            if (tid == 0) st_release_gpu(epoch, (unsigned)t);
        } else {
            if (tid < 32) {
                while (ld_relaxed_gpu(epoch) < (unsigned)t) { }
                (void)ld_acquire_gpu(epoch);
            }
            __syncthreads();
        }

        // fetch current h from L2 (L1 bypass), vectorized
        const float4* hsrc = (const float4*)(hbuf + (t & 1) * H);
        if (tid < H / 4) ((float4*)sh_h)[tid] = __ldcg(hsrc + tid);
        __syncthreads();

        // hg = Whh_slice @ h, all weights in SMEM
        float acc[RW];
#pragma unroll
        for (int j = 0; j < RW; j++) acc[j] = 0.f;

        if (HALF_W) {
#pragma unroll
            for (int kb = 0; kb < H; kb += 256) {       // 8 halves per lane per iter
                float4 ha = *(const float4*)&sh_h[kb + lane * 8];
                float4 hb = *(const float4*)&sh_h[kb + lane * 8 + 4];
#pragma unroll
                for (int j = 0; j < RW; j++) {
                    uint4 wv = *(const uint4*)(wsph[j] + kb);
                    const __half2* h2p = (const __half2*)&wv;
                    float2 f0 = __half22float2(h2p[0]);
                    float2 f1 = __half22float2(h2p[1]);
                    float2 f2 = __half22float2(h2p[2]);
                    float2 f3 = __half22float2(h2p[3]);
                    acc[j] += f0.x * ha.x + f0.y * ha.y + f1.x * ha.z + f1.y * ha.w
                            + f2.x * hb.x + f2.y * hb.y + f3.x * hb.z + f3.y * hb.w;
                }
            }
        } else {
#pragma unroll
            for (int kb = 0; kb < H; kb += 128) {       // 4 floats per lane per iter
                float4 h4 = *(const float4*)&sh_h[kb + lane * 4];
#pragma unroll
                for (int j = 0; j < RW; j++) {
                    float4 w4 = *(const float4*)(wspf[j] + kb);
                    acc[j] += w4.x * h4.x + w4.y * h4.y + w4.z * h4.z + w4.w * h4.w;
                }
            }
        }
#pragma unroll
        for (int j = 0; j < RW; j++) {
#pragma unroll
            for (int off = 16; off > 0; off >>= 1)
                acc[j] += __shfl_xor_sync(0xffffffffu, acc[j], off);
            if (lane == 0) sh_gate[w * RW + j] = acc[j] + sh_bhh[w * RW + j];
        }
        __syncthreads();

        // gate math + state update (S threads)
        if (tid < S) {
            int il = tid;
            float hr = sh_gate[il], hz = sh_gate[S + il], hn = sh_gate[2 * S + il];
            float xr, xz, xn;
            if (MODE == 0) {
                float xt = x[t];
                xr = sh_xa[il] * xt + sh_xb[il];
                xz = sh_xa[S + il] * xt + sh_xb[S + il];
                xn = sh_xa[2 * S + il] * xt + sh_xb[2 * S + il];
            } else if (MODE == 1) {
                xr = pxr; xz = pxz; xn = pxn;
            } else {
                xr = sh_xa[il]; xz = sh_xa[S + il]; xn = sh_xa[2 * S + il];
            }
            float r = 1.f / (1.f + expf(-(xr + hr)));
            float z = 1.f / (1.f + expf(-(xz + hz)));
            float n = tanhf(xn + r * hn);
            float hold = sh_h[c0 + il];
            float hnew = (1.f - z) * n + z * hold;
            hbuf[((t + 1) & 1) * H + c0 + il] = hnew;
            if (STORE_YS) ys[(size_t)t * H + c0 + il] = hnew;
        }

        // ---- arrive: bar.sync orders all writers' stores; tid0 releases flag ----
        __syncthreads();
        if (tid == 0) st_release_gpu(&flags[bid], (unsigned)(t + 1));
    }
}

// ---------------- tiled fp32 GEMM: C[M,N] = A[M,K] @ W[N,K]^T + bias[N] -----------------
__global__ void __launch_bounds__(256, 1) gemm_tn_bias(
    const float* __restrict__ A, const float* __restrict__ W,
    const float* __restrict__ bias, float* __restrict__ C,
    int M, int N, int K)
{
    __shared__ float As[8][128];
    __shared__ float Bs[8][128];
    int tid = threadIdx.x;
    int bm = blockIdx.y * 128, bn = blockIdx.x * 128;
    int lr = tid >> 1;
    int lk = (tid & 1) * 4;
    const float* Ap = A + (size_t)(bm + lr) * K + lk;
    const float* Wp = W + (size_t)(bn + lr) * K + lk;
    int tx = tid & 15, ty = tid >> 4;
    int m0 = ty * 8, n0 = tx * 8;

    float acc[8][8];
#pragma unroll
    for (int i = 0; i < 8; i++)
#pragma unroll
        for (int j = 0; j < 8; j++) acc[i][j] = 0.f;

    for (int k0 = 0; k0 < K; k0 += 8) {
        float4 a4 = *(const float4*)Ap;
        float4 b4 = *(const float4*)Wp;
        Ap += 8; Wp += 8;
        As[lk + 0][lr] = a4.x; As[lk + 1][lr] = a4.y;
        As[lk + 2][lr] = a4.z; As[lk + 3][lr] = a4.w;
        Bs[lk + 0][lr] = b4.x; Bs[lk + 1][lr] = b4.y;
        Bs[lk + 2][lr] = b4.z; Bs[lk + 3][lr] = b4.w;
        __syncthreads();
#pragma unroll
        for (int k = 0; k < 8; k++) {
            float a[8], b[8];
            *(float4*)(a)     = *(const float4*)&As[k][m0];
            *(float4*)(a + 4) = *(const float4*)&As[k][m0 + 4];
            *(float4*)(b)     = *(const float4*)&Bs[k][n0];
            *(float4*)(b + 4) = *(const float4*)&Bs[k][n0 + 4];
#pragma unroll
            for (int i = 0; i < 8; i++)
#pragma unroll
                for (int j = 0; j < 8; j++)
                    acc[i][j] += a[i] * b[j];
        }
        __syncthreads();
    }
#pragma unroll
    for (int i = 0; i < 8; i++) {
        int m = bm + m0 + i;
#pragma unroll
        for (int j = 0; j < 8; j++)
            C[(size_t)m * N + bn + n0 + j] = acc[i][j] + bias[bn + n0 + j];
    }
}

// ---------------- one-shot matvec: out[R] = W[R,K] @ v + b ------------------------------
__global__ void matvec_bias(const float* __restrict__ W, const float* __restrict__ b,
                            const float* __restrict__ v, float* __restrict__ out,
                            int R, int K)
{
    int wid = (blockIdx.x * blockDim.x + threadIdx.x) >> 5;
    int lane = threadIdx.x & 31;
    if (wid >= R) return;
    const float* wr = W + (size_t)wid * K;
    float acc = 0.f;
    for (int k = lane; k < K; k += 32) acc += wr[k] * v[k];
#pragma unroll
    for (int off = 16; off; off >>= 1) acc += __shfl_xor_sync(0xffffffffu, acc, off);
    if (lane == 0) out[wid] = acc + b[wid];
}

// ---------------- final projection: out[t] = ys3[t] . outW + outb ----------------------
__global__ void __launch_bounds__(256) final_out_kernel(
    const float* __restrict__ ys3, const float* __restrict__ outW,
    const float* __restrict__ outb, float* __restrict__ out)
{
    __shared__ float red[8];
    int t = blockIdx.x;
    const float* row = ys3 + (size_t)t * 2048;
    float acc = 0.f;
    for (int k = threadIdx.x; k < 2048; k += 256) acc += row[k] * outW[k];
#pragma unroll
    for (int off = 16; off; off >>= 1) acc += __shfl_xor_sync(0xffffffffu, acc, off);
    if ((threadIdx.x & 31) == 0) red[threadIdx.x >> 5] = acc;
    __syncthreads();
    if (threadIdx.x < 8) {
        float v = red[threadIdx.x];
#pragma unroll
        for (int off = 4; off; off >>= 1) v += __shfl_xor_sync(0xffu, v, off);
        if (threadIdx.x == 0) out[t] = v + outb[0];
    }
}

// ---------------- host ------------------------------------------------------------------
extern "C" void kernel_launch(void* const* d_in, const int* in_sizes, int n_in,
                              void* d_out, int out_size)
{
    const float* x       = (const float*)d_in[0];
    const float* e1_Wih  = (const float*)d_in[1];
    const float* e1_Whh  = (const float*)d_in[2];
    const float* e1_bih  = (const float*)d_in[3];
    const float* e1_bhh  = (const float*)d_in[4];
    const float* e2_Wih  = (const float*)d_in[5];
    const float* e2_Whh  = (const float*)d_in[6];
    const float* e2_bih  = (const float*)d_in[7];
    const float* e2_bhh  = (const float*)d_in[8];
    const float* d1_Wih  = (const float*)d_in[9];
    const float* d1_Whh  = (const float*)d_in[10];
    const float* d1_bih  = (const float*)d_in[11];
    const float* d1_bhh  = (const float*)d_in[12];
    const float* d2_Wih  = (const float*)d_in[13];
    const float* d2_Whh  = (const float*)d_in[14];
    const float* d2_bih  = (const float*)d_in[15];
    const float* d2_bhh  = (const float*)d_in[16];
    const float* out_W   = (const float*)d_in[17];
    const float* out_b   = (const float*)d_in[18];
    float* out = (float*)d_out;

    void *p_ys1, *p_ys2, *p_ys3, *p_xg_e2, *p_xg_d2, *p_xgc;
    void *p_h_e1, *p_h_e2, *p_h_d1, *p_h_d2, *p_we1h, *p_wd2h;
    cudaGetSymbolAddress(&p_ys1, g_ys1);
    cudaGetSymbolAddress(&p_ys2, g_ys2);
    cudaGetSymbolAddress(&p_ys3, g_ys3);
    cudaGetSymbolAddress(&p_xg_e2, g_xg_e2);
    cudaGetSymbolAddress(&p_xg_d2, g_xg_d2);
    cudaGetSymbolAddress(&p_xgc, g_xgc_d1);
    cudaGetSymbolAddress(&p_h_e1, g_h_e1);
    cudaGetSymbolAddress(&p_h_e2, g_h_e2);
    cudaGetSymbolAddress(&p_h_d1, g_h_d1);
    cudaGetSymbolAddress(&p_h_d2, g_h_d2);
    cudaGetSymbolAddress(&p_we1h, g_whh_e1_h);
    cudaGetSymbolAddress(&p_wd2h, g_whh_d2_h);

    // big: H=2048, 128 CTAs, 48 rows/CTA, fp16 fully resident
    const int SMEM_BIG   = (2048 + 4 * 48) * 4 + 48 * 2048 * 2;   // 205,568 B
    // small: H=1024, 64 CTAs, 48 rows/CTA, fp32 fully resident
    const int SMEM_SMALL = (1024 + 4 * 48 + 48 * 1024) * 4;       // 201,472 B

    auto k_e1 = gru_rec_kernel<2048, 128, 512, 0, true,  true>;
    auto k_e2 = gru_rec_kernel<1024,  64, 512, 1, false, false>;
    auto k_d1 = gru_rec_kernel<1024,  64, 512, 2, true,  false>;
    auto k_d2 = gru_rec_kernel<2048, 128, 512, 1, true,  true>;
    cudaFuncSetAttribute(k_e1, cudaFuncAttributeMaxDynamicSharedMemorySize, SMEM_BIG);
    cudaFuncSetAttribute(k_e2, cudaFuncAttributeMaxDynamicSharedMemorySize, SMEM_SMALL);
    cudaFuncSetAttribute(k_d1, cudaFuncAttributeMaxDynamicSharedMemorySize, SMEM_SMALL);
    cudaFuncSetAttribute(k_d2, cudaFuncAttributeMaxDynamicSharedMemorySize, SMEM_BIG);

    init_h_kernel<<<16, 256>>>();

    // one-time fp32 -> fp16 weight conversions (12.58M elems each)
    const int WN = 3 * 2048 * 2048;
    convert_half_kernel<<<(WN / 4 + 255) / 256, 256>>>(e1_Whh, (__half*)p_we1h, WN);
    convert_half_kernel<<<(WN / 4 + 255) / 256, 256>>>(d2_Whh, (__half*)p_wd2h, WN);

    // e1: GRU(1 -> 2048), store ys1
    k_e1<<<128, 512, SMEM_BIG>>>(p_we1h, e1_bhh, nullptr, nullptr,
                                 x, e1_Wih, e1_bih,
                                 (float*)p_h_e1, (float*)p_ys1, 0);

    // xg_e2 = ys1 @ e2_Wih^T + e2_bih   [4096,3072]
    gemm_tn_bias<<<dim3(3072 / 128, T_SEQ / 128), 256>>>(
        (const float*)p_ys1, e2_Wih, e2_bih, (float*)p_xg_e2, T_SEQ, 3072, 2048);

    // e2: GRU(2048 -> 1024), only final hT (lands in g_h_e2[0..1024))
    k_e2<<<64, 512, SMEM_SMALL>>>(e2_Whh, e2_bhh, (const float*)p_xg_e2, nullptr,
                                  nullptr, nullptr, nullptr,
                                  (float*)p_h_e2, nullptr, 1);

    // d1 constant input projection: xgc = d1_Wih @ emb + d1_bih
    matvec_bias<<<(3072 * 32) / 256, 256>>>(d1_Wih, d1_bih, (const float*)p_h_e2,
                                            (float*)p_xgc, 3072, 1024);

    // d1: GRU(1024 -> 1024) with constant xg, store ys2
    k_d1<<<64, 512, SMEM_SMALL>>>(d1_Whh, d1_bhh, nullptr, (const float*)p_xgc,
                                  nullptr, nullptr, nullptr,
                                  (float*)p_h_d1, (float*)p_ys2, 2);

    // xg_d2 = ys2 @ d2_Wih^T + d2_bih   [4096,6144]
    gemm_tn_bias<<<dim3(6144 / 128, T_SEQ / 128), 256>>>(
        (const float*)p_ys2, d2_Wih, d2_bih, (float*)p_xg_d2, T_SEQ, 6144, 1024);

    // d2: GRU(1024 -> 2048), store ys3
    k_d2<<<128, 512, SMEM_BIG>>>(p_wd2h, d2_bhh, (const float*)p_xg_d2, nullptr,
                                 nullptr, nullptr, nullptr,
                                 (float*)p_h_d2, (float*)p_ys3, 3);

    // out[t] = ys3[t] . out_W + out_b
    final_out_kernel<<<T_SEQ, 256>>>((const float*)p_ys3, out_W, out_b, out);
}